// round 16
// baseline (speedup 1.0000x reference)
#include <cuda_runtime.h>
#include <math.h>
#include <stdint.h>

// Problem shapes (fixed by setup_inputs)
#define S_DIM 1024
#define B_DIM 2
#define D_DIM 1024
#define LP1   4
#define H_DIM 16
#define HD    64
#define BHD   (B_DIM * H_DIM)              // 32
#define ROWS  (B_DIM * D_DIM)              // 2048
#define M_X   (S_DIM * B_DIM)              // 2048
#define M_LO  ((LP1 - 1) * S_DIM * B_DIM)  // 6144

#define NE_X   ((size_t)M_X * D_DIM)
#define NE_LO  ((size_t)M_LO * D_DIM)
#define NE_W   ((size_t)D_DIM * D_DIM)
#define NE_KV  ((size_t)LP1 * M_X * D_DIM)

// Global scratch planes
__device__ uint16_t g_xf[NE_X];                      // fp16 inputs
__device__ uint16_t g_lof[NE_LO];
__device__ uint16_t g_Wf[4 * NE_W];                  // fp16 Wq,Wk,Wv,Wo
__device__ uint16_t g_Qf[NE_X];                      // fp16 Q/K/V planes
__device__ uint16_t g_Kf[NE_KV];
__device__ uint16_t g_Vf[NE_KV];
__device__ uint16_t g_Ch[NE_X],  g_Cl[NE_X];         // C accumulator (bf16 split)
__device__ uint16_t g_Cf[NE_X];                      // final C (fp16, for O-proj)

// ---------------------------------------------------------------------------
// Helpers
// ---------------------------------------------------------------------------
__device__ __forceinline__ uint32_t smem_u32(const void* p) {
    uint32_t a;
    asm("{ .reg .u64 t; cvta.to.shared.u64 t, %1; cvt.u32.u64 %0, t; }"
        : "=r"(a) : "l"(p));
    return a;
}
__device__ __forceinline__ uint32_t cvt2bf(float a, float b) {  // {lo=a, hi=b}
    uint32_t r;
    asm("cvt.rn.bf16x2.f32 %0, %1, %2;" : "=r"(r) : "f"(b), "f"(a));
    return r;
}
__device__ __forceinline__ uint32_t cvt2hf(float a, float b) {  // fp16 {lo=a, hi=b}
    uint32_t r;
    asm("cvt.rn.f16x2.f32 %0, %1, %2;" : "=r"(r) : "f"(b), "f"(a));
    return r;
}
__device__ __forceinline__ float bflo(uint32_t p) { return __uint_as_float(p << 16); }
__device__ __forceinline__ float bfhi(uint32_t p) { return __uint_as_float(p & 0xffff0000u); }

__device__ __forceinline__ void ldmx4(uint32_t* r, uint32_t addr) {
    asm volatile("ldmatrix.sync.aligned.m8n8.x4.shared.b16 {%0,%1,%2,%3}, [%4];"
                 : "=r"(r[0]), "=r"(r[1]), "=r"(r[2]), "=r"(r[3]) : "r"(addr));
}
__device__ __forceinline__ void ldmx4t(uint32_t* r, uint32_t addr) {
    asm volatile("ldmatrix.sync.aligned.m8n8.x4.trans.shared.b16 {%0,%1,%2,%3}, [%4];"
                 : "=r"(r[0]), "=r"(r[1]), "=r"(r[2]), "=r"(r[3]) : "r"(addr));
}
__device__ __forceinline__ void mma_f16(float* d, const uint32_t* a,
                                        const uint32_t* b) {
    asm volatile(
        "mma.sync.aligned.m16n8k16.row.col.f32.f16.f16.f32 "
        "{%0,%1,%2,%3}, {%4,%5,%6,%7}, {%8,%9}, {%0,%1,%2,%3};"
        : "+f"(d[0]), "+f"(d[1]), "+f"(d[2]), "+f"(d[3])
        : "r"(a[0]), "r"(a[1]), "r"(a[2]), "r"(a[3]), "r"(b[0]), "r"(b[1]));
}
__device__ __forceinline__ void cp16(uint32_t dst, const void* src) {
    asm volatile("cp.async.cg.shared.global [%0], [%1], 16;"
                 :: "r"(dst), "l"(src));
}
__device__ __forceinline__ void cp_commit() {
    asm volatile("cp.async.commit_group;");
}
__device__ __forceinline__ void cp_wait1() {
    asm volatile("cp.async.wait_group 1;");
}
__device__ __forceinline__ void cp_wait2() {
    asm volatile("cp.async.wait_group 2;");
}

// ---------------------------------------------------------------------------
// Prep: fp32 -> fp16 planes (one launch, 6 jobs).
// ---------------------------------------------------------------------------
#define NSPLIT 6
struct SplitJobs {
    const float4* src[NSPLIT];
    uint2*        dst[NSPLIT];
    int           n4[NSPLIT];
};

__global__ void __launch_bounds__(256) split_all(SplitJobs js) {
    const int j = blockIdx.y;
    const float4* __restrict__ src = js.src[j];
    uint2* __restrict__ dst = js.dst[j];
    const int n4 = js.n4[j];
    for (int i = blockIdx.x * 256 + threadIdx.x; i < n4; i += gridDim.x * 256) {
        float4 v = src[i];
        dst[i] = make_uint2(cvt2hf(v.x, v.y), cvt2hf(v.z, v.w));
    }
}

// ---------------------------------------------------------------------------
// Persistent fp16 single-term GEMM: C = A @ W^T + bias.
// 128x128 CTA tile, 8 warps x (32x64) [4m x 2n], K-chunk 32, 3-stage
// cp.async, 2 CTAs/SM. Output: fp16 plane or fp32 plane.
// ---------------------------------------------------------------------------
struct FJob {
    const uint16_t* Af;
    const uint16_t* Wf;
    const float*    bias;
    uint16_t*       C16;   // fp16 output (or null)
    float*          C32;   // fp32 output (or null)
};
struct FJobs {
    FJob j[5];
    int  start[6];
};

#define FPADK 40
#define F_A 0
#define F_W (128 * FPADK)
#define FSTAGE (256 * FPADK)             // 10240 halves per stage
#define GEMMF_SMEM (3 * FSTAGE * 2)      // 61440 B

__device__ __forceinline__ void f_issue(uint32_t sb, int stage,
                                        const uint16_t* Af_, const uint16_t* Wf_,
                                        int bm, int bn, int k0, int tid) {
    const uint32_t base = sb + (uint32_t)stage * (FSTAGE * 2);
#pragma unroll
    for (int q = 0; q < 2; ++q) {
        int idx = q * 256 + tid;           // 0..511
        int row = idx >> 2;                // 0..127
        int seg = (idx & 3) * 8;
        uint32_t doff = (uint32_t)(row * FPADK + seg) * 2;
        cp16(base + F_A * 2 + doff, Af_ + (size_t)(bm + row) * D_DIM + k0 + seg);
        cp16(base + F_W * 2 + doff, Wf_ + (size_t)(bn + row) * D_DIM + k0 + seg);
    }
}

__global__ void __launch_bounds__(256, 2) gemm_f16_pers(FJobs js) {
    extern __shared__ __align__(16) uint16_t sh[];
    const uint32_t sb = smem_u32(sh);

    const int tid  = threadIdx.x;
    const int wid  = tid >> 5;
    const int lane = tid & 31;
    const int wm   = (wid >> 1) * 32;
    const int wn   = (wid & 1) * 64;
    const int g    = lane >> 3;
    const int r8   = lane & 7;
    const int total = js.start[5];

    for (int t = blockIdx.x; t < total; t += gridDim.x) {
        int jid = 0;
#pragma unroll
        for (int k = 1; k < 5; ++k)
            if (t >= js.start[k]) jid = k;
        const int rem = t - js.start[jid];
        const int bm = (rem >> 3) * 128;
        const int bn = (rem & 7) * 128;
        const uint16_t* __restrict__ Af_ = js.j[jid].Af;
        const uint16_t* __restrict__ Wf_ = js.j[jid].Wf;

        float d[2][8][4];
#pragma unroll
        for (int mi = 0; mi < 2; ++mi)
#pragma unroll
            for (int ni = 0; ni < 8; ++ni)
#pragma unroll
                for (int e = 0; e < 4; ++e) d[mi][ni][e] = 0.f;

        f_issue(sb, 0, Af_, Wf_, bm, bn, 0, tid);
        cp_commit();
        f_issue(sb, 1, Af_, Wf_, bm, bn, 32, tid);
        cp_commit();

        for (int it = 0; it < 32; ++it) {
            cp_wait1();
            __syncthreads();

            const uint32_t bufb = sb + (uint32_t)((it % 3) * FSTAGE) * 2;
#pragma unroll
            for (int ks = 0; ks < 2; ++ks) {
                const int k16 = ks * 16;
                uint32_t af[2][4];
                {
                    const int ar = lane & 15, ac = (lane >> 4) * 8;
#pragma unroll
                    for (int mi = 0; mi < 2; ++mi) {
                        uint32_t off = (uint32_t)((wm + mi * 16 + ar) * FPADK + k16 + ac) * 2;
                        ldmx4(af[mi], bufb + F_A * 2 + off);
                    }
                }
                uint32_t bf4[4][4];
#pragma unroll
                for (int tt = 0; tt < 4; ++tt) {
                    const int row = wn + tt * 16 + (g >> 1) * 8 + r8;
                    const int col = k16 + (g & 1) * 8;
                    uint32_t off = (uint32_t)(row * FPADK + col) * 2;
                    ldmx4(bf4[tt], bufb + F_W * 2 + off);
                }
#pragma unroll
                for (int mi = 0; mi < 2; ++mi)
#pragma unroll
                    for (int ni = 0; ni < 8; ++ni)
                        mma_f16(d[mi][ni], af[mi], &bf4[ni >> 1][(ni & 1) * 2]);
            }

            if (it + 2 < 32)
                f_issue(sb, (it + 2) % 3, Af_, Wf_, bm, bn, (it + 2) * 32, tid);
            cp_commit();
        }

        // ---- epilogue: +bias -> fp16 or fp32 plane ----
        const int qr = lane >> 2;
        const int qc = (lane & 3) * 2;
        const float* bias = js.j[jid].bias;
        uint16_t* C16 = js.j[jid].C16;
        float*    C32 = js.j[jid].C32;
#pragma unroll
        for (int ni = 0; ni < 8; ++ni) {
            const int n0 = bn + wn + ni * 8 + qc;
            const float bx = bias[n0], by = bias[n0 + 1];
#pragma unroll
            for (int mi = 0; mi < 2; ++mi) {
                const int m0 = bm + wm + mi * 16 + qr;
                float v0 = d[mi][ni][0] + bx, v1 = d[mi][ni][1] + by;
                float v2 = d[mi][ni][2] + bx, v3 = d[mi][ni][3] + by;
                if (C16) {
                    *(uint32_t*)(C16 + (size_t)m0 * D_DIM + n0) = cvt2hf(v0, v1);
                    *(uint32_t*)(C16 + (size_t)(m0 + 8) * D_DIM + n0) = cvt2hf(v2, v3);
                }
                if (C32) {
                    *(float2*)(C32 + (size_t)m0 * D_DIM + n0) = make_float2(v0, v1);
                    *(float2*)(C32 + (size_t)(m0 + 8) * D_DIM + n0) = make_float2(v2, v3);
                }
            }
        }
        __syncthreads();   // protect smem stages from next tile's prologue
    }
}

// ---------------------------------------------------------------------------
// Flash attention, fp16 single-term, shift-free softmax (R14/R15-validated).
// Accumulates layers 0-2 into bf16-split Ch/Cl; final layer writes the
// combined result once as a single fp16 plane Cf (feeds fp16 O-proj).
// Grid (BHD, 8): CTA = 128 q-rows, 8 warps x 16 rows, 64-key chunks,
// 3-stage cp.async, 2 CTAs/SM.
// ---------------------------------------------------------------------------
#define ACH 64
#define APD 72
#define APLANE (ACH * APD)
#define ASTAGE (2 * APLANE)
#define ATTN_SMEMF (3 * ASTAGE * 2)     // 55296 B

__device__ __forceinline__ void a_issue(uint32_t sb, int stage,
                                        const uint16_t* Kf_, const uint16_t* Vf_,
                                        int gc, int bh, int tid) {
    const uint32_t base = sb + (uint32_t)stage * (ASTAGE * 2);
    const size_t lbase = (size_t)(gc >> 4) * NE_X;
    const int rbase = (gc & 15) * ACH;
#pragma unroll
    for (int q = 0; q < 2; ++q) {
        int idx = q * 256 + tid;
        int row = idx >> 3;
        int seg = (idx & 7) * 8;
        uint32_t doff = (uint32_t)(row * APD + seg) * 2;
        size_t goff = lbase + (size_t)(rbase + row) * ROWS + bh * HD + seg;
        cp16(base + doff,              Kf_ + goff);
        cp16(base + APLANE * 2 + doff, Vf_ + goff);
    }
}

__global__ void __launch_bounds__(256, 2) attn_f16(
    const uint16_t* __restrict__ Qf_,
    const uint16_t* __restrict__ Kf_, const uint16_t* __restrict__ Vf_,
    const float* __restrict__ lw_in,
    uint16_t* __restrict__ Ch_, uint16_t* __restrict__ Cl_,
    uint16_t* __restrict__ Cf_) {
    extern __shared__ __align__(16) uint16_t ash[];
    const uint32_t sb = smem_u32(ash);

    const int bh    = blockIdx.x;
    const int qbase = blockIdx.y * 128;
    const int tid   = threadIdx.x;
    const int wid   = tid >> 5;
    const int lane  = tid & 31;
    const int wq    = wid * 16;
    const int r     = lane >> 2;
    const int c     = (lane & 3) * 2;
    const int g     = lane >> 3;
    const int r8    = lane & 7;

    uint32_t qf[4][4];
#pragma unroll
    for (int s = 0; s < 4; ++s)
#pragma unroll
        for (int half = 0; half < 2; ++half)
#pragma unroll
            for (int rr = 0; rr < 2; ++rr) {
                const size_t off = (size_t)(qbase + wq + r + rr * 8) * ROWS
                                 + bh * HD + s * 16 + c + half * 8;
                qf[s][rr + half * 2] = *(const uint32_t*)(Qf_ + off);
            }

    float lw[LP1];
    {
        float l0 = lw_in[0], l1 = lw_in[1], l2 = lw_in[2], l3 = lw_in[3];
        float mx = fmaxf(fmaxf(l0, l1), fmaxf(l2, l3));
        float e0 = expf(l0 - mx), e1 = expf(l1 - mx);
        float e2 = expf(l2 - mx), e3 = expf(l3 - mx);
        float inv = 1.f / (e0 + e1 + e2 + e3);
        lw[0] = e0 * inv; lw[1] = e1 * inv; lw[2] = e2 * inv; lw[3] = e3 * inv;
    }

    const float sc = 0.125f * 1.44269504088896340736f;

    a_issue(sb, 0, Kf_, Vf_, 0, bh, tid);
    cp_commit();
    a_issue(sb, 1, Kf_, Vf_, 1, bh, tid);
    cp_commit();
    a_issue(sb, 2, Kf_, Vf_, 2, bh, tid);
    cp_commit();

    float sum0 = 0.f, sum1 = 0.f;
    float o[8][4];

    for (int gc = 0; gc < LP1 * 16; ++gc) {
        if ((gc & 15) == 0) {
            sum0 = sum1 = 0.f;
#pragma unroll
            for (int j = 0; j < 8; ++j)
#pragma unroll
                for (int e = 0; e < 4; ++e) o[j][e] = 0.f;
        }

        cp_wait2();
        __syncthreads();
        const uint32_t bufb = sb + (uint32_t)((gc % 3) * ASTAGE) * 2;

        float sv[8][4];
#pragma unroll
        for (int j = 0; j < 8; ++j)
#pragma unroll
            for (int e = 0; e < 4; ++e) sv[j][e] = 0.f;

#pragma unroll
        for (int ks = 0; ks < 4; ++ks) {
#pragma unroll
            for (int nt2 = 0; nt2 < 4; ++nt2) {
                const int nrow = nt2 * 16 + (g >> 1) * 8 + r8;
                const int ncol = ks * 16 + (g & 1) * 8;
                const uint32_t off = (uint32_t)(nrow * APD + ncol) * 2;
                uint32_t kf[4];
                ldmx4(kf, bufb + off);
                mma_f16(sv[2 * nt2],     qf[ks], &kf[0]);
                mma_f16(sv[2 * nt2 + 1], qf[ks], &kf[2]);
            }
        }

        // ---- P = exp2(S*sc)  (shift-free; scores O(1)) ----
#pragma unroll
        for (int ks2 = 0; ks2 < 4; ++ks2) {
            const float* se = sv[2 * ks2];
            const float* so = sv[2 * ks2 + 1];
            float p00 = exp2f(se[0] * sc);
            float p01 = exp2f(se[1] * sc);
            float p02 = exp2f(se[2] * sc);
            float p03 = exp2f(se[3] * sc);
            float p10 = exp2f(so[0] * sc);
            float p11 = exp2f(so[1] * sc);
            float p12 = exp2f(so[2] * sc);
            float p13 = exp2f(so[3] * sc);
            sum0 += (p00 + p01) + (p10 + p11);
            sum1 += (p02 + p03) + (p12 + p13);
            uint32_t pf[4];
            pf[0] = cvt2hf(p00, p01);
            pf[1] = cvt2hf(p02, p03);
            pf[2] = cvt2hf(p10, p11);
            pf[3] = cvt2hf(p12, p13);

#pragma unroll
            for (int ntv = 0; ntv < 4; ++ntv) {
                const int krow = ks2 * 16 + (g & 1) * 8 + r8;
                const int vcol = ntv * 16 + (g >> 1) * 8;
                const uint32_t off = (uint32_t)(krow * APD + vcol) * 2;
                uint32_t vf[4];
                ldmx4t(vf, bufb + APLANE * 2 + off);
                mma_f16(o[2 * ntv],     pf, &vf[0]);
                mma_f16(o[2 * ntv + 1], pf, &vf[2]);
            }
        }

        __syncthreads();
        if (gc + 3 < LP1 * 16)
            a_issue(sb, gc % 3, Kf_, Vf_, gc + 3, bh, tid);
        cp_commit();

        // ---- end of layer: accumulate into Ch/Cl; last layer -> Cf (fp16) ----
        if ((gc & 15) == 15) {
            const int l = gc >> 4;
            float s0 = sum0, s1 = sum1;
            s0 += __shfl_xor_sync(0xffffffffu, s0, 1);
            s0 += __shfl_xor_sync(0xffffffffu, s0, 2);
            s1 += __shfl_xor_sync(0xffffffffu, s1, 1);
            s1 += __shfl_xor_sync(0xffffffffu, s1, 2);
            const float w0 = lw[l] / s0, w1 = lw[l] / s1;
            const int g0 = qbase + wq + r;
#pragma unroll
            for (int j = 0; j < 8; ++j) {
                size_t off0 = (size_t)g0 * ROWS + bh * HD + j * 8 + c;
                size_t off1 = (size_t)(g0 + 8) * ROWS + bh * HD + j * 8 + c;
                float v0 = w0 * o[j][0], v1 = w0 * o[j][1];
                float v2 = w1 * o[j][2], v3 = w1 * o[j][3];
                if (l != 0) {
                    uint32_t h0 = *(uint32_t*)(Ch_ + off0), l0w = *(uint32_t*)(Cl_ + off0);
                    uint32_t h1 = *(uint32_t*)(Ch_ + off1), l1w = *(uint32_t*)(Cl_ + off1);
                    v0 += bflo(h0) + bflo(l0w); v1 += bfhi(h0) + bfhi(l0w);
                    v2 += bflo(h1) + bflo(l1w); v3 += bfhi(h1) + bfhi(l1w);
                }
                if (l != LP1 - 1) {
                    uint32_t h0 = cvt2bf(v0, v1), h1 = cvt2bf(v2, v3);
                    uint32_t l0w = cvt2bf(v0 - bflo(h0), v1 - bfhi(h0));
                    uint32_t l1w = cvt2bf(v2 - bflo(h1), v3 - bfhi(h1));
                    *(uint32_t*)(Ch_ + off0) = h0; *(uint32_t*)(Cl_ + off0) = l0w;
                    *(uint32_t*)(Ch_ + off1) = h1; *(uint32_t*)(Cl_ + off1) = l1w;
                } else {
                    *(uint32_t*)(Cf_ + off0) = cvt2hf(v0, v1);
                    *(uint32_t*)(Cf_ + off1) = cvt2hf(v2, v3);
                }
            }
        }
    }
}

// ---------------------------------------------------------------------------
extern "C" void kernel_launch(void* const* d_in, const int* in_sizes, int n_in,
                              void* d_out, int out_size) {
    const float* x  = (const float*)d_in[0];
    const float* lo = (const float*)d_in[1];
    const float* Wq = (const float*)d_in[2];
    const float* bq = (const float*)d_in[3];
    const float* Wk = (const float*)d_in[4];
    const float* bk = (const float*)d_in[5];
    const float* Wv = (const float*)d_in[6];
    const float* bv = (const float*)d_in[7];
    const float* Wo = (const float*)d_in[8];
    const float* bo = (const float*)d_in[9];
    const float* lw = (const float*)d_in[10];
    float* out = (float*)d_out;

    uint16_t *xf, *lof, *Wf;
    uint16_t *Qf, *Kf, *Vf, *Ch, *Cl, *Cf;
    cudaGetSymbolAddress((void**)&xf, g_xf);
    cudaGetSymbolAddress((void**)&lof, g_lof);
    cudaGetSymbolAddress((void**)&Wf, g_Wf);
    cudaGetSymbolAddress((void**)&Qf, g_Qf);
    cudaGetSymbolAddress((void**)&Kf, g_Kf);
    cudaGetSymbolAddress((void**)&Vf, g_Vf);
    cudaGetSymbolAddress((void**)&Ch, g_Ch);
    cudaGetSymbolAddress((void**)&Cl, g_Cl);
    cudaGetSymbolAddress((void**)&Cf, g_Cf);

    cudaFuncSetAttribute(gemm_f16_pers, cudaFuncAttributeMaxDynamicSharedMemorySize,
                         GEMMF_SMEM);
    cudaFuncSetAttribute(attn_f16, cudaFuncAttributeMaxDynamicSharedMemorySize,
                         ATTN_SMEMF);

    // 0) convert all inputs to fp16 planes (single launch)
    {
        SplitJobs js;
        js.src[0] = (const float4*)x;  js.dst[0] = (uint2*)xf;
        js.n4[0] = (int)(NE_X / 4);
        js.src[1] = (const float4*)lo; js.dst[1] = (uint2*)lof;
        js.n4[1] = (int)(NE_LO / 4);
        js.src[2] = (const float4*)Wq; js.dst[2] = (uint2*)(Wf + 0 * NE_W);
        js.n4[2] = (int)(NE_W / 4);
        js.src[3] = (const float4*)Wk; js.dst[3] = (uint2*)(Wf + 1 * NE_W);
        js.n4[3] = (int)(NE_W / 4);
        js.src[4] = (const float4*)Wv; js.dst[4] = (uint2*)(Wf + 2 * NE_W);
        js.n4[4] = (int)(NE_W / 4);
        js.src[5] = (const float4*)Wo; js.dst[5] = (uint2*)(Wf + 3 * NE_W);
        js.n4[5] = (int)(NE_W / 4);
        split_all<<<dim3(2048, NSPLIT), 256>>>(js);
    }

    // 1+2) all Q/K/V projections — persistent fp16 gemm, 1152 tiles, 296 CTAs.
    {
        FJobs js;
        js.j[0] = { xf,  Wf + 0 * NE_W, bq, Qf, nullptr };
        js.j[1] = { xf,  Wf + 1 * NE_W, bk, Kf, nullptr };
        js.j[2] = { xf,  Wf + 2 * NE_W, bv, Vf, nullptr };
        js.j[3] = { lof, Wf + 1 * NE_W, bk, Kf + NE_X, nullptr };
        js.j[4] = { lof, Wf + 2 * NE_W, bv, Vf + NE_X, nullptr };
        js.start[0] = 0;   js.start[1] = 128; js.start[2] = 256;
        js.start[3] = 384; js.start[4] = 768; js.start[5] = 1152;
        gemm_f16_pers<<<296, 256, GEMMF_SMEM>>>(js);
    }
    // 3) attention -> Cf (fp16 final combined plane)
    attn_f16<<<dim3(BHD, 8), 256, ATTN_SMEMF>>>(Qf, Kf, Vf, lw, Ch, Cl, Cf);
    // 4) Cf @ Wo^T + bo -> out (fp16 single-term, 128 tiles, one wave)
    {
        FJobs js;
        js.j[0] = { Cf, Wf + 3 * NE_W, bo, nullptr, out };
        js.j[1] = js.j[0]; js.j[2] = js.j[0]; js.j[3] = js.j[0]; js.j[4] = js.j[0];
        js.start[0] = 0;   js.start[1] = 128; js.start[2] = 128;
        js.start[3] = 128; js.start[4] = 128; js.start[5] = 128;
        gemm_f16_pers<<<128, 256, GEMMF_SMEM>>>(js);
    }
}

// round 17
// speedup vs baseline: 1.0173x; 1.0173x over previous
#include <cuda_runtime.h>
#include <math.h>
#include <stdint.h>

// Problem shapes (fixed by setup_inputs)
#define S_DIM 1024
#define B_DIM 2
#define D_DIM 1024
#define LP1   4
#define H_DIM 16
#define HD    64
#define BHD   (B_DIM * H_DIM)              // 32
#define ROWS  (B_DIM * D_DIM)              // 2048
#define M_X   (S_DIM * B_DIM)              // 2048
#define M_LO  ((LP1 - 1) * S_DIM * B_DIM)  // 6144

#define NE_X   ((size_t)M_X * D_DIM)
#define NE_LO  ((size_t)M_LO * D_DIM)
#define NE_W   ((size_t)D_DIM * D_DIM)
#define NE_KV  ((size_t)LP1 * M_X * D_DIM)

// Global scratch planes
__device__ uint16_t g_xf[NE_X];                      // fp16 inputs
__device__ uint16_t g_lof[NE_LO];
__device__ uint16_t g_Wf[4 * NE_W];                  // fp16 Wq,Wk,Wv,Wo
__device__ uint16_t g_Qf[NE_X];                      // fp16 Q/K/V planes
__device__ uint16_t g_Kf[NE_KV];
__device__ uint16_t g_Vf[NE_KV];
__device__ uint16_t g_Ch[NE_X],  g_Cl[NE_X];         // C accumulator (bf16 split)
__device__ uint16_t g_Cf[NE_X];                      // final C (fp16, for O-proj)

// ---------------------------------------------------------------------------
// Helpers
// ---------------------------------------------------------------------------
__device__ __forceinline__ uint32_t smem_u32(const void* p) {
    uint32_t a;
    asm("{ .reg .u64 t; cvta.to.shared.u64 t, %1; cvt.u32.u64 %0, t; }"
        : "=r"(a) : "l"(p));
    return a;
}
__device__ __forceinline__ uint32_t cvt2bf(float a, float b) {  // {lo=a, hi=b}
    uint32_t r;
    asm("cvt.rn.bf16x2.f32 %0, %1, %2;" : "=r"(r) : "f"(b), "f"(a));
    return r;
}
__device__ __forceinline__ uint32_t cvt2hf(float a, float b) {  // fp16 {lo=a, hi=b}
    uint32_t r;
    asm("cvt.rn.f16x2.f32 %0, %1, %2;" : "=r"(r) : "f"(b), "f"(a));
    return r;
}
__device__ __forceinline__ float bflo(uint32_t p) { return __uint_as_float(p << 16); }
__device__ __forceinline__ float bfhi(uint32_t p) { return __uint_as_float(p & 0xffff0000u); }

__device__ __forceinline__ void ldmx4(uint32_t* r, uint32_t addr) {
    asm volatile("ldmatrix.sync.aligned.m8n8.x4.shared.b16 {%0,%1,%2,%3}, [%4];"
                 : "=r"(r[0]), "=r"(r[1]), "=r"(r[2]), "=r"(r[3]) : "r"(addr));
}
__device__ __forceinline__ void ldmx4t(uint32_t* r, uint32_t addr) {
    asm volatile("ldmatrix.sync.aligned.m8n8.x4.trans.shared.b16 {%0,%1,%2,%3}, [%4];"
                 : "=r"(r[0]), "=r"(r[1]), "=r"(r[2]), "=r"(r[3]) : "r"(addr));
}
__device__ __forceinline__ void mma_f16(float* d, const uint32_t* a,
                                        const uint32_t* b) {
    asm volatile(
        "mma.sync.aligned.m16n8k16.row.col.f32.f16.f16.f32 "
        "{%0,%1,%2,%3}, {%4,%5,%6,%7}, {%8,%9}, {%0,%1,%2,%3};"
        : "+f"(d[0]), "+f"(d[1]), "+f"(d[2]), "+f"(d[3])
        : "r"(a[0]), "r"(a[1]), "r"(a[2]), "r"(a[3]), "r"(b[0]), "r"(b[1]));
}
__device__ __forceinline__ void cp16(uint32_t dst, const void* src) {
    asm volatile("cp.async.cg.shared.global [%0], [%1], 16;"
                 :: "r"(dst), "l"(src));
}
__device__ __forceinline__ void cp_commit() {
    asm volatile("cp.async.commit_group;");
}
__device__ __forceinline__ void cp_wait1() {
    asm volatile("cp.async.wait_group 1;");
}
__device__ __forceinline__ void cp_wait2() {
    asm volatile("cp.async.wait_group 2;");
}

// ---------------------------------------------------------------------------
// Prep: fp32 -> fp16 planes (one launch, 6 jobs).
// ---------------------------------------------------------------------------
#define NSPLIT 6
struct SplitJobs {
    const float4* src[NSPLIT];
    uint2*        dst[NSPLIT];
    int           n4[NSPLIT];
};

__global__ void __launch_bounds__(256) split_all(SplitJobs js) {
    const int j = blockIdx.y;
    const float4* __restrict__ src = js.src[j];
    uint2* __restrict__ dst = js.dst[j];
    const int n4 = js.n4[j];
    for (int i = blockIdx.x * 256 + threadIdx.x; i < n4; i += gridDim.x * 256) {
        float4 v = src[i];
        dst[i] = make_uint2(cvt2hf(v.x, v.y), cvt2hf(v.z, v.w));
    }
}

// ---------------------------------------------------------------------------
// Persistent fp16 single-term GEMM: C = A @ W^T + bias.
// 128x256 CTA tile, 512 threads / 16 warps x (32x64) [4m x 4n], K-chunk 32,
// 3-stage cp.async, 1 CTA/SM. Flat tile list over up to 5 jobs.
// ---------------------------------------------------------------------------
struct FJob {
    const uint16_t* Af;
    const uint16_t* Wf;
    const float*    bias;
    uint16_t*       C16;   // fp16 output (or null)
    float*          C32;   // fp32 output (or null)
};
struct FJobs {
    FJob j[5];
    int  start[6];
};

#define FPADK 40
#define F_A 0
#define F_W (128 * FPADK)                // A plane 128 rows; W plane 256 rows
#define FSTAGE (384 * FPADK)             // 15360 halves per stage
#define GEMMF_SMEM (3 * FSTAGE * 2)      // 92160 B

__device__ __forceinline__ void f_issue(uint32_t sb, int stage,
                                        const uint16_t* Af_, const uint16_t* Wf_,
                                        int bm, int bn, int k0, int tid) {
    const uint32_t base = sb + (uint32_t)stage * (FSTAGE * 2);
    {   // A: 128 rows x 4 segs = 512 loads (one per thread)
        int row = tid >> 2;
        int seg = (tid & 3) * 8;
        uint32_t doff = (uint32_t)(row * FPADK + seg) * 2;
        cp16(base + F_A * 2 + doff, Af_ + (size_t)(bm + row) * D_DIM + k0 + seg);
    }
#pragma unroll
    for (int q = 0; q < 2; ++q) {  // W: 256 rows x 4 segs = 1024 loads
        int idx = q * 512 + tid;
        int row = idx >> 2;
        int seg = (idx & 3) * 8;
        uint32_t doff = (uint32_t)(row * FPADK + seg) * 2;
        cp16(base + F_W * 2 + doff, Wf_ + (size_t)(bn + row) * D_DIM + k0 + seg);
    }
}

__global__ void __launch_bounds__(512, 1) gemm_f16_pers(FJobs js) {
    extern __shared__ __align__(16) uint16_t sh[];
    const uint32_t sb = smem_u32(sh);

    const int tid  = threadIdx.x;
    const int wid  = tid >> 5;            // 0..15
    const int lane = tid & 31;
    const int wm   = (wid >> 2) * 32;     // 0,32,64,96
    const int wn   = (wid & 3) * 64;      // 0,64,128,192
    const int g    = lane >> 3;
    const int r8   = lane & 7;
    const int total = js.start[5];

    for (int t = blockIdx.x; t < total; t += gridDim.x) {
        int jid = 0;
#pragma unroll
        for (int k = 1; k < 5; ++k)
            if (t >= js.start[k]) jid = k;
        const int rem = t - js.start[jid];
        const int bm = (rem >> 2) * 128;
        const int bn = (rem & 3) * 256;
        const uint16_t* __restrict__ Af_ = js.j[jid].Af;
        const uint16_t* __restrict__ Wf_ = js.j[jid].Wf;

        float d[2][8][4];
#pragma unroll
        for (int mi = 0; mi < 2; ++mi)
#pragma unroll
            for (int ni = 0; ni < 8; ++ni)
#pragma unroll
                for (int e = 0; e < 4; ++e) d[mi][ni][e] = 0.f;

        f_issue(sb, 0, Af_, Wf_, bm, bn, 0, tid);
        cp_commit();
        f_issue(sb, 1, Af_, Wf_, bm, bn, 32, tid);
        cp_commit();

        for (int it = 0; it < 32; ++it) {
            cp_wait1();
            __syncthreads();

            const uint32_t bufb = sb + (uint32_t)((it % 3) * FSTAGE) * 2;
#pragma unroll
            for (int ks = 0; ks < 2; ++ks) {
                const int k16 = ks * 16;
                uint32_t af[2][4];
                {
                    const int ar = lane & 15, ac = (lane >> 4) * 8;
#pragma unroll
                    for (int mi = 0; mi < 2; ++mi) {
                        uint32_t off = (uint32_t)((wm + mi * 16 + ar) * FPADK + k16 + ac) * 2;
                        ldmx4(af[mi], bufb + F_A * 2 + off);
                    }
                }
                uint32_t bf4[4][4];
#pragma unroll
                for (int tt = 0; tt < 4; ++tt) {
                    const int row = wn + tt * 16 + (g >> 1) * 8 + r8;
                    const int col = k16 + (g & 1) * 8;
                    uint32_t off = (uint32_t)(row * FPADK + col) * 2;
                    ldmx4(bf4[tt], bufb + F_W * 2 + off);
                }
#pragma unroll
                for (int mi = 0; mi < 2; ++mi)
#pragma unroll
                    for (int ni = 0; ni < 8; ++ni)
                        mma_f16(d[mi][ni], af[mi], &bf4[ni >> 1][(ni & 1) * 2]);
            }

            if (it + 2 < 32)
                f_issue(sb, (it + 2) % 3, Af_, Wf_, bm, bn, (it + 2) * 32, tid);
            cp_commit();
        }

        // ---- epilogue: +bias -> fp16 or fp32 plane ----
        const int qr = lane >> 2;
        const int qc = (lane & 3) * 2;
        const float* bias = js.j[jid].bias;
        uint16_t* C16 = js.j[jid].C16;
        float*    C32 = js.j[jid].C32;
#pragma unroll
        for (int ni = 0; ni < 8; ++ni) {
            const int n0 = bn + wn + ni * 8 + qc;
            const float bx = bias[n0], by = bias[n0 + 1];
#pragma unroll
            for (int mi = 0; mi < 2; ++mi) {
                const int m0 = bm + wm + mi * 16 + qr;
                float v0 = d[mi][ni][0] + bx, v1 = d[mi][ni][1] + by;
                float v2 = d[mi][ni][2] + bx, v3 = d[mi][ni][3] + by;
                if (C16) {
                    *(uint32_t*)(C16 + (size_t)m0 * D_DIM + n0) = cvt2hf(v0, v1);
                    *(uint32_t*)(C16 + (size_t)(m0 + 8) * D_DIM + n0) = cvt2hf(v2, v3);
                }
                if (C32) {
                    *(float2*)(C32 + (size_t)m0 * D_DIM + n0) = make_float2(v0, v1);
                    *(float2*)(C32 + (size_t)(m0 + 8) * D_DIM + n0) = make_float2(v2, v3);
                }
            }
        }
        __syncthreads();   // protect smem stages from next tile's prologue
    }
}

// ---------------------------------------------------------------------------
// Flash attention, fp16 single-term, shift-free softmax.
// 512 threads / 16 warps x 16 q-rows => 256-q-row CTA; grid (BHD, 4) = 128
// CTAs, one wave; halves K/V L2 traffic vs 128-row CTAs. Per-warp microkernel
// identical to R14/R16. 64-key chunks, 3-stage cp.async, 1 CTA/SM.
// Layers 0-2 accumulate into bf16-split Ch/Cl; last layer writes fp16 Cf.
// ---------------------------------------------------------------------------
#define ACH 64
#define APD 72
#define APLANE (ACH * APD)
#define ASTAGE (2 * APLANE)
#define ATTN_SMEMF (3 * ASTAGE * 2)     // 55296 B

__device__ __forceinline__ void a_issue(uint32_t sb, int stage,
                                        const uint16_t* Kf_, const uint16_t* Vf_,
                                        int gc, int bh, int tid) {
    const uint32_t base = sb + (uint32_t)stage * (ASTAGE * 2);
    const size_t lbase = (size_t)(gc >> 4) * NE_X;
    const int rbase = (gc & 15) * ACH;
    // 64 rows x 8 segs = 512 loads per plane; one K + one V per thread
    int row = tid >> 3;
    int seg = (tid & 7) * 8;
    uint32_t doff = (uint32_t)(row * APD + seg) * 2;
    size_t goff = lbase + (size_t)(rbase + row) * ROWS + bh * HD + seg;
    cp16(base + doff,              Kf_ + goff);
    cp16(base + APLANE * 2 + doff, Vf_ + goff);
}

__global__ void __launch_bounds__(512, 1) attn_f16(
    const uint16_t* __restrict__ Qf_,
    const uint16_t* __restrict__ Kf_, const uint16_t* __restrict__ Vf_,
    const float* __restrict__ lw_in,
    uint16_t* __restrict__ Ch_, uint16_t* __restrict__ Cl_,
    uint16_t* __restrict__ Cf_) {
    extern __shared__ __align__(16) uint16_t ash[];
    const uint32_t sb = smem_u32(ash);

    const int bh    = blockIdx.x;
    const int qbase = blockIdx.y * 256;
    const int tid   = threadIdx.x;
    const int wid   = tid >> 5;           // 0..15
    const int lane  = tid & 31;
    const int wq    = wid * 16;           // 0..240
    const int r     = lane >> 2;
    const int c     = (lane & 3) * 2;
    const int g     = lane >> 3;
    const int r8    = lane & 7;

    uint32_t qf[4][4];
#pragma unroll
    for (int s = 0; s < 4; ++s)
#pragma unroll
        for (int half = 0; half < 2; ++half)
#pragma unroll
            for (int rr = 0; rr < 2; ++rr) {
                const size_t off = (size_t)(qbase + wq + r + rr * 8) * ROWS
                                 + bh * HD + s * 16 + c + half * 8;
                qf[s][rr + half * 2] = *(const uint32_t*)(Qf_ + off);
            }

    float lw[LP1];
    {
        float l0 = lw_in[0], l1 = lw_in[1], l2 = lw_in[2], l3 = lw_in[3];
        float mx = fmaxf(fmaxf(l0, l1), fmaxf(l2, l3));
        float e0 = expf(l0 - mx), e1 = expf(l1 - mx);
        float e2 = expf(l2 - mx), e3 = expf(l3 - mx);
        float inv = 1.f / (e0 + e1 + e2 + e3);
        lw[0] = e0 * inv; lw[1] = e1 * inv; lw[2] = e2 * inv; lw[3] = e3 * inv;
    }

    const float sc = 0.125f * 1.44269504088896340736f;

    a_issue(sb, 0, Kf_, Vf_, 0, bh, tid);
    cp_commit();
    a_issue(sb, 1, Kf_, Vf_, 1, bh, tid);
    cp_commit();
    a_issue(sb, 2, Kf_, Vf_, 2, bh, tid);
    cp_commit();

    float sum0 = 0.f, sum1 = 0.f;
    float o[8][4];

    for (int gc = 0; gc < LP1 * 16; ++gc) {
        if ((gc & 15) == 0) {
            sum0 = sum1 = 0.f;
#pragma unroll
            for (int j = 0; j < 8; ++j)
#pragma unroll
                for (int e = 0; e < 4; ++e) o[j][e] = 0.f;
        }

        cp_wait2();
        __syncthreads();
        const uint32_t bufb = sb + (uint32_t)((gc % 3) * ASTAGE) * 2;

        float sv[8][4];
#pragma unroll
        for (int j = 0; j < 8; ++j)
#pragma unroll
            for (int e = 0; e < 4; ++e) sv[j][e] = 0.f;

#pragma unroll
        for (int ks = 0; ks < 4; ++ks) {
#pragma unroll
            for (int nt2 = 0; nt2 < 4; ++nt2) {
                const int nrow = nt2 * 16 + (g >> 1) * 8 + r8;
                const int ncol = ks * 16 + (g & 1) * 8;
                const uint32_t off = (uint32_t)(nrow * APD + ncol) * 2;
                uint32_t kf[4];
                ldmx4(kf, bufb + off);
                mma_f16(sv[2 * nt2],     qf[ks], &kf[0]);
                mma_f16(sv[2 * nt2 + 1], qf[ks], &kf[2]);
            }
        }

        // ---- P = exp2(S*sc)  (shift-free; scores O(1)) ----
#pragma unroll
        for (int ks2 = 0; ks2 < 4; ++ks2) {
            const float* se = sv[2 * ks2];
            const float* so = sv[2 * ks2 + 1];
            float p00 = exp2f(se[0] * sc);
            float p01 = exp2f(se[1] * sc);
            float p02 = exp2f(se[2] * sc);
            float p03 = exp2f(se[3] * sc);
            float p10 = exp2f(so[0] * sc);
            float p11 = exp2f(so[1] * sc);
            float p12 = exp2f(so[2] * sc);
            float p13 = exp2f(so[3] * sc);
            sum0 += (p00 + p01) + (p10 + p11);
            sum1 += (p02 + p03) + (p12 + p13);
            uint32_t pf[4];
            pf[0] = cvt2hf(p00, p01);
            pf[1] = cvt2hf(p02, p03);
            pf[2] = cvt2hf(p10, p11);
            pf[3] = cvt2hf(p12, p13);

#pragma unroll
            for (int ntv = 0; ntv < 4; ++ntv) {
                const int krow = ks2 * 16 + (g & 1) * 8 + r8;
                const int vcol = ntv * 16 + (g >> 1) * 8;
                const uint32_t off = (uint32_t)(krow * APD + vcol) * 2;
                uint32_t vf[4];
                ldmx4t(vf, bufb + APLANE * 2 + off);
                mma_f16(o[2 * ntv],     pf, &vf[0]);
                mma_f16(o[2 * ntv + 1], pf, &vf[2]);
            }
        }

        __syncthreads();
        if (gc + 3 < LP1 * 16)
            a_issue(sb, gc % 3, Kf_, Vf_, gc + 3, bh, tid);
        cp_commit();

        // ---- end of layer: accumulate into Ch/Cl; last layer -> Cf (fp16) ----
        if ((gc & 15) == 15) {
            const int l = gc >> 4;
            float s0 = sum0, s1 = sum1;
            s0 += __shfl_xor_sync(0xffffffffu, s0, 1);
            s0 += __shfl_xor_sync(0xffffffffu, s0, 2);
            s1 += __shfl_xor_sync(0xffffffffu, s1, 1);
            s1 += __shfl_xor_sync(0xffffffffu, s1, 2);
            const float w0 = lw[l] / s0, w1 = lw[l] / s1;
            const int g0 = qbase + wq + r;
#pragma unroll
            for (int j = 0; j < 8; ++j) {
                size_t off0 = (size_t)g0 * ROWS + bh * HD + j * 8 + c;
                size_t off1 = (size_t)(g0 + 8) * ROWS + bh * HD + j * 8 + c;
                float v0 = w0 * o[j][0], v1 = w0 * o[j][1];
                float v2 = w1 * o[j][2], v3 = w1 * o[j][3];
                if (l != 0) {
                    uint32_t h0 = *(uint32_t*)(Ch_ + off0), l0w = *(uint32_t*)(Cl_ + off0);
                    uint32_t h1 = *(uint32_t*)(Ch_ + off1), l1w = *(uint32_t*)(Cl_ + off1);
                    v0 += bflo(h0) + bflo(l0w); v1 += bfhi(h0) + bfhi(l0w);
                    v2 += bflo(h1) + bflo(l1w); v3 += bfhi(h1) + bfhi(l1w);
                }
                if (l != LP1 - 1) {
                    uint32_t h0 = cvt2bf(v0, v1), h1 = cvt2bf(v2, v3);
                    uint32_t l0w = cvt2bf(v0 - bflo(h0), v1 - bfhi(h0));
                    uint32_t l1w = cvt2bf(v2 - bflo(h1), v3 - bfhi(h1));
                    *(uint32_t*)(Ch_ + off0) = h0; *(uint32_t*)(Cl_ + off0) = l0w;
                    *(uint32_t*)(Ch_ + off1) = h1; *(uint32_t*)(Cl_ + off1) = l1w;
                } else {
                    *(uint32_t*)(Cf_ + off0) = cvt2hf(v0, v1);
                    *(uint32_t*)(Cf_ + off1) = cvt2hf(v2, v3);
                }
            }
        }
    }
}

// ---------------------------------------------------------------------------
extern "C" void kernel_launch(void* const* d_in, const int* in_sizes, int n_in,
                              void* d_out, int out_size) {
    const float* x  = (const float*)d_in[0];
    const float* lo = (const float*)d_in[1];
    const float* Wq = (const float*)d_in[2];
    const float* bq = (const float*)d_in[3];
    const float* Wk = (const float*)d_in[4];
    const float* bk = (const float*)d_in[5];
    const float* Wv = (const float*)d_in[6];
    const float* bv = (const float*)d_in[7];
    const float* Wo = (const float*)d_in[8];
    const float* bo = (const float*)d_in[9];
    const float* lw = (const float*)d_in[10];
    float* out = (float*)d_out;

    uint16_t *xf, *lof, *Wf;
    uint16_t *Qf, *Kf, *Vf, *Ch, *Cl, *Cf;
    cudaGetSymbolAddress((void**)&xf, g_xf);
    cudaGetSymbolAddress((void**)&lof, g_lof);
    cudaGetSymbolAddress((void**)&Wf, g_Wf);
    cudaGetSymbolAddress((void**)&Qf, g_Qf);
    cudaGetSymbolAddress((void**)&Kf, g_Kf);
    cudaGetSymbolAddress((void**)&Vf, g_Vf);
    cudaGetSymbolAddress((void**)&Ch, g_Ch);
    cudaGetSymbolAddress((void**)&Cl, g_Cl);
    cudaGetSymbolAddress((void**)&Cf, g_Cf);

    cudaFuncSetAttribute(gemm_f16_pers, cudaFuncAttributeMaxDynamicSharedMemorySize,
                         GEMMF_SMEM);
    cudaFuncSetAttribute(attn_f16, cudaFuncAttributeMaxDynamicSharedMemorySize,
                         ATTN_SMEMF);

    // 0) convert all inputs to fp16 planes (single launch)
    {
        SplitJobs js;
        js.src[0] = (const float4*)x;  js.dst[0] = (uint2*)xf;
        js.n4[0] = (int)(NE_X / 4);
        js.src[1] = (const float4*)lo; js.dst[1] = (uint2*)lof;
        js.n4[1] = (int)(NE_LO / 4);
        js.src[2] = (const float4*)Wq; js.dst[2] = (uint2*)(Wf + 0 * NE_W);
        js.n4[2] = (int)(NE_W / 4);
        js.src[3] = (const float4*)Wk; js.dst[3] = (uint2*)(Wf + 1 * NE_W);
        js.n4[3] = (int)(NE_W / 4);
        js.src[4] = (const float4*)Wv; js.dst[4] = (uint2*)(Wf + 2 * NE_W);
        js.n4[4] = (int)(NE_W / 4);
        js.src[5] = (const float4*)Wo; js.dst[5] = (uint2*)(Wf + 3 * NE_W);
        js.n4[5] = (int)(NE_W / 4);
        split_all<<<dim3(2048, NSPLIT), 256>>>(js);
    }

    // 1+2) all Q/K/V projections — persistent fp16 gemm, 576 128x256 tiles,
    //      148 CTAs (1/SM, 16 warps).
    {
        FJobs js;
        js.j[0] = { xf,  Wf + 0 * NE_W, bq, Qf, nullptr };
        js.j[1] = { xf,  Wf + 1 * NE_W, bk, Kf, nullptr };
        js.j[2] = { xf,  Wf + 2 * NE_W, bv, Vf, nullptr };
        js.j[3] = { lof, Wf + 1 * NE_W, bk, Kf + NE_X, nullptr };
        js.j[4] = { lof, Wf + 2 * NE_W, bv, Vf + NE_X, nullptr };
        js.start[0] = 0;   js.start[1] = 64;  js.start[2] = 128;
        js.start[3] = 192; js.start[4] = 384; js.start[5] = 576;
        gemm_f16_pers<<<148, 512, GEMMF_SMEM>>>(js);
    }
    // 3) attention (256-q-row CTAs) -> Cf (fp16 final combined plane)
    attn_f16<<<dim3(BHD, S_DIM / 256), 512, ATTN_SMEMF>>>(Qf, Kf, Vf, lw,
                                                          Ch, Cl, Cf);
    // 4) Cf @ Wo^T + bo -> out (fp16 single-term, 64 tiles)
    {
        FJobs js;
        js.j[0] = { Cf, Wf + 3 * NE_W, bo, nullptr, out };
        js.j[1] = js.j[0]; js.j[2] = js.j[0]; js.j[3] = js.j[0]; js.j[4] = js.j[0];
        js.start[0] = 0;  js.start[1] = 64; js.start[2] = 64;
        js.start[3] = 64; js.start[4] = 64; js.start[5] = 64;
        gemm_f16_pers<<<64, 512, GEMMF_SMEM>>>(js);
    }
}